// round 7
// baseline (speedup 1.0000x reference)
#include <cuda_runtime.h>
#include <cuda_fp16.h>
#include <cstdint>

// ---------------- Problem constants ----------------
#define NB   16
#define NI   256
#define NO   512
#define WD   512
#define PXY  4225      // 65*65
#define NSTG 72        // 9 taps * 8 chunks of 32 channels (tensor path)

#define NFFMA   136    // ffma CTAs, 2 tiles each (64x64)
#define NTENS   444    // tensor CTAs: 111 m-tiles x 4 n-tiles
#define MSPLIT  14208  // rows >= MSPLIT handled by ffma path (17 m-tiles)

// ---------------- Device scratch ----------------
__device__ float  g_styles[NB * NI];
__device__ float  g_wsq[NO * NI];
__device__ float  g_dcoefs[NB * NO];
__device__ __half g_Bh[NO * 9 * NI];             // [o][tap*256 + i]
__device__ __half g_xth[(size_t)NB * PXY * NI];  // NHWC: [n][y*65+x][i]

__device__ __forceinline__ uint32_t smem_u32(const void* p) {
    return (uint32_t)__cvta_generic_to_shared(p);
}
__device__ __forceinline__ void cp16(uint32_t dst, const void* src) {
    asm volatile("cp.async.cg.shared.global [%0], [%1], 16;\n" :: "r"(dst), "l"(src));
}

// ---------------- K1: styles ----------------
__global__ void k_styles(const float* __restrict__ w,
                         const float* __restrict__ aw,
                         const float* __restrict__ ab) {
    __shared__ float sw[WD];
    const int n = blockIdx.x;
    const int i = threadIdx.x;
    for (int d = threadIdx.x; d < WD; d += 256) sw[d] = w[n * WD + d];
    __syncthreads();
    const float* __restrict__ row = aw + (size_t)i * WD;
    float acc = 0.f;
#pragma unroll 8
    for (int d = 0; d < WD; d++) acc += sw[d] * row[d];
    g_styles[n * NI + i] = acc * 0.04419417382415922f + ab[i];
}

// ---------------- K2: pack weight -> Bh[o][t*256+i] (fp16) + wsq ----------------
__global__ void k_pack(const float* __restrict__ weight) {
    const int gt = blockIdx.x * 256 + threadIdx.x;   // 131072
    const int i = gt & (NI - 1);
    const int o = gt >> 8;
    const float* __restrict__ src = weight + ((size_t)o * NI + i) * 9;
    float s = 0.f;
#pragma unroll
    for (int t = 0; t < 9; t++) {
        float v = src[t];
        s += v * v;
        g_Bh[(size_t)o * (9 * NI) + t * NI + i] = __float2half(v);
    }
    g_wsq[o * NI + i] = s;
}

// ---------------- K3: dcoefs ----------------
__global__ void k_dcoefs() {
    __shared__ float s2[NI];
    const int n = blockIdx.x;
    const int o = threadIdx.x;  // 512
    if (o < NI) { float s = g_styles[n * NI + o]; s2[o] = s * s; }
    __syncthreads();
    const float* __restrict__ wr = g_wsq + (size_t)o * NI;
    float acc = 0.f;
#pragma unroll 8
    for (int i = 0; i < NI; i++) acc += s2[i] * wr[i];
    g_dcoefs[n * NO + o] = rsqrtf(acc + 1e-8f);
}

// ---------------- K4: fused FIR + modulate + NHWC transpose ----------------
#define FW 69
#define SROW (16 * FW)
__global__ __launch_bounds__(256) void k_fir2(const float* __restrict__ x) {
    extern __shared__ float sf[];    // 16*16*69 floats = 70656 B
    const int tid = threadIdx.x;
    const int y0 = blockIdx.x * 13;
    const int i0 = blockIdx.y << 4;
    const int n  = blockIdx.z;
    const float f0 = 0.125f, f1 = 0.375f;

    {
        int idx = tid;
#pragma unroll
        for (int it = 0; it < 4; it++, idx += 256) {
            int c4 = idx & 3;
            int ch = (idx >> 2) & 15;
            int r  = idx >> 6;
            int c  = (c4 < 2) ? c4 : 64 + c4;
            sf[r * SROW + ch * FW + c] = 0.f;
        }
    }
#pragma unroll
    for (int r = 0; r < 16; r++) {
        int g = y0 - 2 + r;
        if (g < 0 || g > 63) {
            for (int idx = tid; idx < 16 * FW; idx += 256)
                sf[r * SROW + idx] = 0.f;
        }
    }
    {
        const float* __restrict__ xb = x + (((size_t)(n << 8) + i0) << 12);
#pragma unroll
        for (int it = 0; it < 16; it++) {
            int idx = it * 256 + tid;
            int q  = idx & 15;
            int ch = (idx >> 4) & 15;
            int r  = idx >> 8;
            int g  = y0 - 2 + r;
            if (g >= 0 && g <= 63) {
                const float4 v = *(const float4*)(xb + ((size_t)ch << 12) + (g << 6) + (q << 2));
                float* d = &sf[r * SROW + ch * FW + 2 + (q << 2)];
                d[0] = v.x; d[1] = v.y; d[2] = v.z; d[3] = v.w;
            }
        }
    }
    __syncthreads();

    const int ch = tid & 15;
    const int q  = tid >> 4;
    const float st = g_styles[(n << 8) + i0 + ch];
    __half* __restrict__ outp = g_xth + ((size_t)n * PXY << 8) + i0 + ch;
#pragma unroll
    for (int j = 0; j < 5; j++) {
        const int xc = q + (j << 4);
        if (xc > 64) break;
        float h[16];
#pragma unroll
        for (int r = 0; r < 16; r++) {
            const float* s = &sf[r * SROW + ch * FW + xc];
            h[r] = f0 * (s[0] + s[3]) + f1 * (s[1] + s[2]);
        }
#pragma unroll
        for (int y = 0; y < 13; y++) {
            float v = f0 * (h[y] + h[y + 3]) + f1 * (h[y + 1] + h[y + 2]);
            outp[(size_t)(((y0 + y) * 65 + xc)) << 8] = __float2half(v * st);
        }
    }
}

// ---------------- K5: hybrid GEMM: tensor CTAs + FFMA CTAs in one launch ----------------
__device__ __forceinline__ void mma_f16(float c[4], const uint32_t a[4], const uint32_t b[2]) {
    asm volatile(
        "mma.sync.aligned.m16n8k16.row.col.f32.f16.f16.f32 "
        "{%0,%1,%2,%3}, {%4,%5,%6,%7}, {%8,%9}, {%0,%1,%2,%3};\n"
        : "+f"(c[0]), "+f"(c[1]), "+f"(c[2]), "+f"(c[3])
        : "r"(a[0]), "r"(a[1]), "r"(a[2]), "r"(a[3]), "r"(b[0]), "r"(b[1]));
}

__global__ __launch_bounds__(256, 2) void k_gemm(const float* __restrict__ bias,
                                                 float* __restrict__ out) {
    extern __shared__ __align__(16) char dsm[];
    const int tid = threadIdx.x;
    const int bx = blockIdx.x;
    const float SQ2 = 1.4142135623730951f;

    if (bx < NFFMA) {
        // ============ FFMA path: two 64x64 tiles, fp32 SGEMM ============
        float (*Af)[16][68] = (float(*)[16][68])dsm;                    // [2][16][68]
        float (*Bf)[16][68] = (float(*)[16][68])(dsm + 2 * 16 * 68 * 4);
        const int ty = tid >> 4, tx = tid & 15;
        const int r0 = ty << 2, c0 = tx << 2;
        const int lr = tid >> 2, lq = tid & 3;

        for (int j = 0; j < 2; j++) {
            const int tau = (bx << 1) + j;           // 0..271
            const int nb = tau / 34, rb = tau % 34;
            const int mrow = MSPLIT + (rb << 6);
            const int obase = nb << 6;
            const int n_img = mrow >> 10;
            const __half* __restrict__ xn = g_xth + (size_t)n_img * PXY * NI;
            const int m = mrow + lr;
            const int oh = (m >> 5) & 31, ow = m & 31;
            const __half* __restrict__ brow = g_Bh + (size_t)(obase + lr) * (9 * NI) + (lq << 2);

            float acc[4][4];
#pragma unroll
            for (int i = 0; i < 4; i++)
#pragma unroll
                for (int c = 0; c < 4; c++) acc[i][c] = 0.f;

            uint2 ra, rbv;
            auto ldg_stage = [&](int s) {
                const int t = s >> 4;
                const int ta = t / 3, tb = t - ta * 3;
                const int chb = (s & 15) << 4;
                const int y  = (oh << 1) + 2 - ta;
                const int xx = (ow << 1) + 2 - tb;
                ra  = *(const uint2*)(xn + (((size_t)(y * 65 + xx)) << 8) + chb + (lq << 2));
                rbv = *(const uint2*)(brow + (t << 8) + chb);
            };
            auto sts_stage = [&](int b) {
                const __half* ha = (const __half*)&ra;
                const __half* hb = (const __half*)&rbv;
#pragma unroll
                for (int u = 0; u < 4; u++) {
                    Af[b][(lq << 2) + u][lr] = __half2float(ha[u]);
                    Bf[b][(lq << 2) + u][lr] = __half2float(hb[u]);
                }
            };

            ldg_stage(0); sts_stage(0); __syncthreads();
            for (int s = 0; s < 144; s++) {
                const int b = s & 1;
                if (s + 1 < 144) ldg_stage(s + 1);
#pragma unroll 4
                for (int k = 0; k < 16; k++) {
                    float4 av = *(const float4*)&Af[b][k][r0];
                    float4 bv = *(const float4*)&Bf[b][k][c0];
                    acc[0][0] += av.x * bv.x; acc[0][1] += av.x * bv.y;
                    acc[0][2] += av.x * bv.z; acc[0][3] += av.x * bv.w;
                    acc[1][0] += av.y * bv.x; acc[1][1] += av.y * bv.y;
                    acc[1][2] += av.y * bv.z; acc[1][3] += av.y * bv.w;
                    acc[2][0] += av.z * bv.x; acc[2][1] += av.z * bv.y;
                    acc[2][2] += av.z * bv.z; acc[2][3] += av.z * bv.w;
                    acc[3][0] += av.w * bv.x; acc[3][1] += av.w * bv.y;
                    acc[3][2] += av.w * bv.z; acc[3][3] += av.w * bv.w;
                }
                __syncthreads();
                if (s + 1 < 144) { sts_stage(b ^ 1); }
                __syncthreads();
            }
#pragma unroll
            for (int i = 0; i < 4; i++) {
                const int mm = mrow + r0 + i;
                const int sp = mm & 1023;
#pragma unroll
                for (int c = 0; c < 4; c++) {
                    const int o = obase + c0 + c;
                    float v = acc[i][c] * g_dcoefs[(n_img << 9) + o] + bias[o];
                    v = (v >= 0.f ? v : 0.2f * v) * SQ2;
                    out[(((size_t)(n_img << 9) + o) << 10) + sp] = v;
                }
            }
            __syncthreads();
        }
        return;
    }

    // ============ Tensor path: 128x128 tile, fp16 mma.m16n8k16 ============
    typedef __half (*TileT)[128][40];
    TileT As = (TileT)dsm;                // [2][128][40] halfs = 20480 B
    TileT Bs = (TileT)(dsm + 20480);

    const int t  = bx - NFFMA;            // 0..443
    const int lane = tid & 31, wid = tid >> 5;
    const int wm = wid & 1, wn = wid >> 1;
    const int mblk = (t >> 2) << 7;       // m-tiles 0..110
    const int obase = (t & 3) << 7;
    const int n_img = mblk >> 10;
    const int g = lane >> 2, t4 = lane & 3;

    const int lr = tid >> 1;
    const int hq = (tid & 1) << 4;
    const int m  = mblk + lr;
    const int oh = (m >> 5) & 31, ow = m & 31;
    const __half* __restrict__ xn = g_xth + (size_t)n_img * PXY * NI;
    const __half* __restrict__ bw = g_Bh + (size_t)(obase + lr) * (9 * NI) + hq;

    float acc[4][4][4];
#pragma unroll
    for (int a = 0; a < 4; a++)
#pragma unroll
        for (int b = 0; b < 4; b++)
#pragma unroll
            for (int e = 0; e < 4; e++) acc[a][b][e] = 0.f;

    auto load_stage = [&](int s, int b) {
        const int tp = s >> 3, c = s & 7;
        const int ta = tp / 3, tb = tp - ta * 3;
        const int y  = (oh << 1) + 2 - ta;
        const int xx = (ow << 1) + 2 - tb;
        const __half* asrc = xn + (((size_t)(y * 65 + xx)) << 8) + (c << 5) + hq;
        uint32_t ad = smem_u32(&As[b][lr][hq]);
        cp16(ad, asrc);
        cp16(ad + 16, asrc + 8);
        const __half* bsrc = bw + (tp << 8) + (c << 5);
        uint32_t bd = smem_u32(&Bs[b][lr][hq]);
        cp16(bd, bsrc);
        cp16(bd + 16, bsrc + 8);
    };

    load_stage(0, 0);
    asm volatile("cp.async.commit_group;\n" ::: "memory");

    for (int s = 0; s < NSTG; s++) {
        const int b = s & 1;
        if (s + 1 < NSTG) load_stage(s + 1, b ^ 1);
        asm volatile("cp.async.commit_group;\n" ::: "memory");
        asm volatile("cp.async.wait_group 1;\n" ::: "memory");
        __syncthreads();
#pragma unroll
        for (int kk = 0; kk < 32; kk += 16) {
            uint32_t af[4][4], bf[4][2];
#pragma unroll
            for (int mf = 0; mf < 4; mf++) {
                int r = (wm << 6) + (mf << 4) + g;
                int kc = kk + (t4 << 1);
                af[mf][0] = *(const uint32_t*)&As[b][r][kc];
                af[mf][1] = *(const uint32_t*)&As[b][r + 8][kc];
                af[mf][2] = *(const uint32_t*)&As[b][r][kc + 8];
                af[mf][3] = *(const uint32_t*)&As[b][r + 8][kc + 8];
            }
#pragma unroll
            for (int nf = 0; nf < 4; nf++) {
                int c = (wn << 5) + (nf << 3) + g;
                int kc = kk + (t4 << 1);
                bf[nf][0] = *(const uint32_t*)&Bs[b][c][kc];
                bf[nf][1] = *(const uint32_t*)&Bs[b][c][kc + 8];
            }
#pragma unroll
            for (int mf = 0; mf < 4; mf++)
#pragma unroll
                for (int nf = 0; nf < 4; nf++)
                    mma_f16(acc[mf][nf], af[mf], bf[nf]);
        }
        __syncthreads();
    }

#pragma unroll
    for (int mf = 0; mf < 4; mf++) {
#pragma unroll
        for (int half = 0; half < 2; half++) {
            int mm = mblk + (wm << 6) + (mf << 4) + g + (half << 3);
            int sp = mm & 1023;
#pragma unroll
            for (int nf = 0; nf < 4; nf++) {
                int o0 = obase + (wn << 5) + (nf << 3) + (t4 << 1);
#pragma unroll
                for (int e = 0; e < 2; e++) {
                    int o = o0 + e;
                    float v = acc[mf][nf][half * 2 + e];
                    float d = g_dcoefs[(n_img << 9) + o];
                    float val = v * d + bias[o];
                    val = (val >= 0.f ? val : 0.2f * val) * SQ2;
                    out[(((size_t)(n_img << 9) + o) << 10) + sp] = val;
                }
            }
        }
    }
}

// ---------------- Launch ----------------
extern "C" void kernel_launch(void* const* d_in, const int* in_sizes, int n_in,
                              void* d_out, int out_size) {
    const float* x      = (const float*)d_in[0];  // [16,256,64,64]
    const float* w      = (const float*)d_in[1];  // [16,512]
    const float* aw     = (const float*)d_in[2];  // [256,512]
    const float* ab     = (const float*)d_in[3];  // [256]
    const float* weight = (const float*)d_in[4];  // [512,256,3,3]
    const float* bias   = (const float*)d_in[5];  // [512]
    float* out = (float*)d_out;                   // [16,512,32,32]

    cudaFuncSetAttribute(k_fir2, cudaFuncAttributeMaxDynamicSharedMemorySize, 70656);

    k_styles<<<16, 256>>>(w, aw, ab);
    k_pack<<<512, 256>>>(weight);
    k_dcoefs<<<16, 512>>>();
    k_fir2<<<dim3(5, 16, 16), 256, 70656>>>(x);
    k_gemm<<<NFFMA + NTENS, 256, 40960>>>(bias, out);
}

// round 8
// speedup vs baseline: 1.4984x; 1.4984x over previous
#include <cuda_runtime.h>
#include <cuda_fp16.h>
#include <cstdint>

// ---------------- Problem constants ----------------
#define NB   16
#define NI   256
#define NO   512
#define WD   512
#define PXY  4225      // 65*65
#define NSTG 72        // 9 taps * 8 chunks of 32 channels

// ---------------- Device scratch ----------------
__device__ float  g_styles[NB * NI];
__device__ float  g_wsq[NO * NI];
__device__ float  g_dcoefs[NB * NO];
__device__ __half g_Bh[NO * 9 * NI];             // [o][tap*256 + i]
__device__ __half g_xth[(size_t)NB * PXY * NI];  // NHWC: [n][y*65+x][i]

__device__ __forceinline__ uint32_t smem_u32(const void* p) {
    return (uint32_t)__cvta_generic_to_shared(p);
}
__device__ __forceinline__ void cp16(uint32_t dst, const void* src) {
    asm volatile("cp.async.cg.shared.global [%0], [%1], 16;\n" :: "r"(dst), "l"(src));
}
__device__ __forceinline__ void ldsm_x4(uint32_t d[4], uint32_t addr) {
    asm volatile("ldmatrix.sync.aligned.m8n8.x4.shared.b16 {%0,%1,%2,%3}, [%4];\n"
                 : "=r"(d[0]), "=r"(d[1]), "=r"(d[2]), "=r"(d[3]) : "r"(addr));
}
__device__ __forceinline__ void ldsm_x2(uint32_t d[2], uint32_t addr) {
    asm volatile("ldmatrix.sync.aligned.m8n8.x2.shared.b16 {%0,%1}, [%2];\n"
                 : "=r"(d[0]), "=r"(d[1]) : "r"(addr));
}

// ---------------- K1: styles ----------------
__global__ void k_styles(const float* __restrict__ w,
                         const float* __restrict__ aw,
                         const float* __restrict__ ab) {
    __shared__ float sw[WD];
    const int n = blockIdx.x;
    const int i = threadIdx.x;
    for (int d = threadIdx.x; d < WD; d += 256) sw[d] = w[n * WD + d];
    __syncthreads();
    const float* __restrict__ row = aw + (size_t)i * WD;
    float acc = 0.f;
#pragma unroll 8
    for (int d = 0; d < WD; d++) acc += sw[d] * row[d];
    g_styles[n * NI + i] = acc * 0.04419417382415922f + ab[i];
}

// ---------------- K2: pack weight -> Bh[o][t*256+i] (fp16) + wsq ----------------
__global__ void k_pack(const float* __restrict__ weight) {
    const int gt = blockIdx.x * 256 + threadIdx.x;   // 131072
    const int i = gt & (NI - 1);
    const int o = gt >> 8;
    const float* __restrict__ src = weight + ((size_t)o * NI + i) * 9;
    float s = 0.f;
#pragma unroll
    for (int t = 0; t < 9; t++) {
        float v = src[t];
        s += v * v;
        g_Bh[(size_t)o * (9 * NI) + t * NI + i] = __float2half(v);
    }
    g_wsq[o * NI + i] = s;
}

// ---------------- K3: dcoefs ----------------
__global__ void k_dcoefs() {
    __shared__ float s2[NI];
    const int n = blockIdx.x;
    const int o = threadIdx.x;  // 512
    if (o < NI) { float s = g_styles[n * NI + o]; s2[o] = s * s; }
    __syncthreads();
    const float* __restrict__ wr = g_wsq + (size_t)o * NI;
    float acc = 0.f;
#pragma unroll 8
    for (int i = 0; i < NI; i++) acc += s2[i] * wr[i];
    g_dcoefs[n * NO + o] = rsqrtf(acc + 1e-8f);
}

// ---------------- K4: fused FIR + modulate + NHWC transpose ----------------
#define FW 69
#define SROW (16 * FW)
__global__ __launch_bounds__(256) void k_fir2(const float* __restrict__ x) {
    extern __shared__ float sf[];    // 16*16*69 floats = 70656 B
    const int tid = threadIdx.x;
    const int y0 = blockIdx.x * 13;
    const int i0 = blockIdx.y << 4;
    const int n  = blockIdx.z;
    const float f0 = 0.125f, f1 = 0.375f;

    {
        int idx = tid;
#pragma unroll
        for (int it = 0; it < 4; it++, idx += 256) {
            int c4 = idx & 3;
            int ch = (idx >> 2) & 15;
            int r  = idx >> 6;
            int c  = (c4 < 2) ? c4 : 64 + c4;
            sf[r * SROW + ch * FW + c] = 0.f;
        }
    }
#pragma unroll
    for (int r = 0; r < 16; r++) {
        int g = y0 - 2 + r;
        if (g < 0 || g > 63) {
            for (int idx = tid; idx < 16 * FW; idx += 256)
                sf[r * SROW + idx] = 0.f;
        }
    }
    {
        const float* __restrict__ xb = x + (((size_t)(n << 8) + i0) << 12);
#pragma unroll
        for (int it = 0; it < 16; it++) {
            int idx = it * 256 + tid;
            int q  = idx & 15;
            int ch = (idx >> 4) & 15;
            int r  = idx >> 8;
            int g  = y0 - 2 + r;
            if (g >= 0 && g <= 63) {
                const float4 v = *(const float4*)(xb + ((size_t)ch << 12) + (g << 6) + (q << 2));
                float* d = &sf[r * SROW + ch * FW + 2 + (q << 2)];
                d[0] = v.x; d[1] = v.y; d[2] = v.z; d[3] = v.w;
            }
        }
    }
    __syncthreads();

    const int ch = tid & 15;
    const int q  = tid >> 4;
    const float st = g_styles[(n << 8) + i0 + ch];
    __half* __restrict__ outp = g_xth + ((size_t)n * PXY << 8) + i0 + ch;
#pragma unroll
    for (int j = 0; j < 5; j++) {
        const int xc = q + (j << 4);
        if (xc > 64) break;
        float h[16];
#pragma unroll
        for (int r = 0; r < 16; r++) {
            const float* s = &sf[r * SROW + ch * FW + xc];
            h[r] = f0 * (s[0] + s[3]) + f1 * (s[1] + s[2]);
        }
#pragma unroll
        for (int y = 0; y < 13; y++) {
            float v = f0 * (h[y] + h[y + 3]) + f1 * (h[y + 1] + h[y + 2]);
            outp[(size_t)(((y0 + y) * 65 + xc)) << 8] = __float2half(v * st);
        }
    }
}

// ---------------- K5: fp16 implicit-GEMM conv, 3-stage pipeline + ldmatrix ----------------
// C[16384, 512] = A[16384, 2304] * B[2304, 512]; tile 128x128x32, 8 warps (2x4).
// smem: 3 buffers x (A 128x40 halfs + B 128x40 halfs) = 61440 B dynamic.
#define BUFB 20480u   // bytes per buffer (A 10240 + B 10240)
__device__ __forceinline__ void mma_f16(float c[4], const uint32_t a[4], const uint32_t b[2]) {
    asm volatile(
        "mma.sync.aligned.m16n8k16.row.col.f32.f16.f16.f32 "
        "{%0,%1,%2,%3}, {%4,%5,%6,%7}, {%8,%9}, {%0,%1,%2,%3};\n"
        : "+f"(c[0]), "+f"(c[1]), "+f"(c[2]), "+f"(c[3])
        : "r"(a[0]), "r"(a[1]), "r"(a[2]), "r"(a[3]), "r"(b[0]), "r"(b[1]));
}

__global__ __launch_bounds__(256, 2) void k_gemm(const float* __restrict__ bias,
                                                 float* __restrict__ out) {
    extern __shared__ __align__(16) char dsm[];
    const uint32_t sbase = smem_u32(dsm);

    const int tid  = threadIdx.x;
    const int lane = tid & 31, wid = tid >> 5;
    const int wm = wid & 1, wn = wid >> 1;            // 2 x 4 warp grid
    const int mblk = blockIdx.x << 7;                 // within one image
    const int obase = blockIdx.y << 7;
    const int n_img = mblk >> 10;
    const int g = lane >> 2, t4 = lane & 3;

    // gmem load mapping: thread t -> row lr = t>>1, 32B at half-offset hq
    const int lr = tid >> 1;
    const int hq = (tid & 1) << 4;
    const int m  = mblk + lr;
    const int oh = (m >> 5) & 31, ow = m & 31;
    const __half* __restrict__ xn = g_xth + (size_t)n_img * PXY * NI;
    const __half* __restrict__ bw = g_Bh + (size_t)(obase + lr) * (9 * NI) + hq;

    // ldmatrix lane-address bases (per-buffer offsets added later)
    // A: row = wm*64 + (lane&15) (+ mf*16), col halfs = kk + ((lane>>4)*8)
    const uint32_t aOff = (uint32_t)(wm * 64 + (lane & 15)) * 80u + (uint32_t)((lane >> 4) << 3) * 2u;
    // B: row = wn*32 + (lane&7) (+ nf*8), col halfs = kk + ((lane>>3)&1)*8
    const uint32_t bOff = 10240u + (uint32_t)(wn * 32 + (lane & 7)) * 80u
                        + (uint32_t)(((lane >> 3) & 1) << 3) * 2u;
    // cp.async destinations within a buffer
    const uint32_t aDst = (uint32_t)lr * 80u + (uint32_t)hq * 2u;
    const uint32_t bDst = 10240u + aDst;

    float acc[4][4][4];
#pragma unroll
    for (int a = 0; a < 4; a++)
#pragma unroll
        for (int b = 0; b < 4; b++)
#pragma unroll
            for (int e = 0; e < 4; e++) acc[a][b][e] = 0.f;

    auto load_stage = [&](int s, uint32_t bufU) {
        const int tp = s >> 3, c = s & 7;
        const int ta = tp / 3, tb = tp - ta * 3;
        const int y  = (oh << 1) + 2 - ta;
        const int xx = (ow << 1) + 2 - tb;
        const __half* asrc = xn + (((size_t)(y * 65 + xx)) << 8) + (c << 5) + hq;
        cp16(bufU + aDst, asrc);
        cp16(bufU + aDst + 16, asrc + 8);
        const __half* bsrc = bw + (tp << 8) + (c << 5);
        cp16(bufU + bDst, bsrc);
        cp16(bufU + bDst + 16, bsrc + 8);
    };

    load_stage(0, sbase);
    asm volatile("cp.async.commit_group;\n" ::: "memory");
    load_stage(1, sbase + BUFB);
    asm volatile("cp.async.commit_group;\n" ::: "memory");

    uint32_t bufIdx = 0;        // s % 3
    for (int s = 0; s < NSTG; s++) {
        asm volatile("cp.async.wait_group 1;\n" ::: "memory");
        __syncthreads();
        if (s + 2 < NSTG) {
            uint32_t nb = bufIdx + 2; if (nb >= 3) nb -= 3;
            load_stage(s + 2, sbase + nb * BUFB);
        }
        asm volatile("cp.async.commit_group;\n" ::: "memory");

        const uint32_t bufU = sbase + bufIdx * BUFB;
        const uint32_t aB = bufU + aOff;
        const uint32_t bB = bufU + bOff;
#pragma unroll
        for (int kk = 0; kk < 32; kk += 16) {
            uint32_t af[4][4], bf[4][2];
#pragma unroll
            for (int mf = 0; mf < 4; mf++)
                ldsm_x4(af[mf], aB + (uint32_t)(mf * 16) * 80u + (uint32_t)kk * 2u);
#pragma unroll
            for (int nf = 0; nf < 4; nf++)
                ldsm_x2(bf[nf], bB + (uint32_t)(nf * 8) * 80u + (uint32_t)kk * 2u);
#pragma unroll
            for (int mf = 0; mf < 4; mf++)
#pragma unroll
                for (int nf = 0; nf < 4; nf++)
                    mma_f16(acc[mf][nf], af[mf], bf[nf]);
        }
        if (++bufIdx == 3) bufIdx = 0;
    }

    // Epilogue: y = lrelu(acc * dcoefs[n,o] + bias[o]) * sqrt(2)
    const float SQ2 = 1.4142135623730951f;
#pragma unroll
    for (int mf = 0; mf < 4; mf++) {
#pragma unroll
        for (int half = 0; half < 2; half++) {
            int mm = mblk + (wm << 6) + (mf << 4) + g + (half << 3);
            int sp = mm & 1023;
#pragma unroll
            for (int nf = 0; nf < 4; nf++) {
                int o0 = obase + (wn << 5) + (nf << 3) + (t4 << 1);
#pragma unroll
                for (int e = 0; e < 2; e++) {
                    int o = o0 + e;
                    float v = acc[mf][nf][half * 2 + e];
                    float d = g_dcoefs[(n_img << 9) + o];
                    float val = v * d + bias[o];
                    val = (val >= 0.f ? val : 0.2f * val) * SQ2;
                    out[(((size_t)(n_img << 9) + o) << 10) + sp] = val;
                }
            }
        }
    }
}

// ---------------- Launch ----------------
extern "C" void kernel_launch(void* const* d_in, const int* in_sizes, int n_in,
                              void* d_out, int out_size) {
    const float* x      = (const float*)d_in[0];  // [16,256,64,64]
    const float* w      = (const float*)d_in[1];  // [16,512]
    const float* aw     = (const float*)d_in[2];  // [256,512]
    const float* ab     = (const float*)d_in[3];  // [256]
    const float* weight = (const float*)d_in[4];  // [512,256,3,3]
    const float* bias   = (const float*)d_in[5];  // [512]
    float* out = (float*)d_out;                   // [16,512,32,32]

    cudaFuncSetAttribute(k_fir2, cudaFuncAttributeMaxDynamicSharedMemorySize, 70656);
    cudaFuncSetAttribute(k_gemm, cudaFuncAttributeMaxDynamicSharedMemorySize, 61440);

    k_styles<<<16, 256>>>(w, aw, ab);
    k_pack<<<512, 256>>>(weight);
    k_dcoefs<<<16, 512>>>();
    k_fir2<<<dim3(5, 16, 16), 256, 70656>>>(x);
    k_gemm<<<dim3(128, 4), 256, 61440>>>(bias, out);
}